// round 10
// baseline (speedup 1.0000x reference)
#include <cuda_runtime.h>
#include <cstdint>
#include <cstddef>

#define NUM_USERS 10000
#define EMBED_DIM 64
#define BATCH     4096
#define TM        128            // b rows per CTA
#define CK        64             // u per chunk
#define SPLITS    9
#define NCH       157            // ceil(10000/64)
#define NTILES    (BATCH / TM)   // 32

// smem buffer layout (bf16 tiles, 128B rows, xor-swizzled)
#define OFF_AHI   0              // A hi: 128 rows x 64 bf16 = 16KB
#define OFF_ALO   16384
#define OFF_BHI   32768          // B hi: 64 rows (u) x 64 bf16 = 8KB
#define OFF_BLO   40960
#define BUF_STRIDE 49152
#define DSM_SIZE  (2 * BUF_STRIDE)   // 96KB

// Precomputed E (bf16 hi/lo), stored as the exact swizzled smem image:
// row u (padded to 157*64), 128 bytes; byte b of logical row stored at b^((u&7)<<4).
#define BROWS (NCH * CK)         // 10048
__device__ __align__(16) unsigned char g_Bhi[BROWS * 128];
__device__ __align__(16) unsigned char g_Blo[BROWS * 128];
__device__ float        g_partials[SPLITS][BATCH];
__device__ unsigned int g_cnt[NTILES];

// ---------------- helpers ----------------
__device__ __forceinline__ uint32_t smem_u32(const void* p) {
    uint32_t a;
    asm("{ .reg .u64 t; cvta.to.shared.u64 t, %1; cvt.u32.u64 %0, t; }" : "=r"(a) : "l"(p));
    return a;
}
__device__ __forceinline__ uint32_t pack_bf2(float a, float b) {
    uint32_t r;
    asm("{\n\t.reg .b16 l, h;\n\t"
        "cvt.rn.bf16.f32 l, %1;\n\t"
        "cvt.rn.bf16.f32 h, %2;\n\t"
        "mov.b32 %0, {l, h};\n\t}"
        : "=r"(r) : "f"(a), "f"(b));
    return r;
}
__device__ __forceinline__ float bfu_lo(uint32_t p) { return __uint_as_float(p << 16); }
__device__ __forceinline__ float bfu_hi(uint32_t p) { return __uint_as_float(p & 0xFFFF0000u); }

__device__ __forceinline__ void sts16(uint32_t a, uint32_t x, uint32_t y, uint32_t z, uint32_t w) {
    asm volatile("st.shared.v4.b32 [%0], {%1, %2, %3, %4};" :: "r"(a), "r"(x), "r"(y), "r"(z), "r"(w));
}
__device__ __forceinline__ void ldsm_x4(uint32_t* r, uint32_t a) {
    asm volatile("ldmatrix.sync.aligned.m8n8.x4.shared.b16 {%0,%1,%2,%3}, [%4];"
        : "=r"(r[0]), "=r"(r[1]), "=r"(r[2]), "=r"(r[3]) : "r"(a));
}
__device__ __forceinline__ void ldsm_x4t(uint32_t* r, uint32_t a) {
    asm volatile("ldmatrix.sync.aligned.m8n8.x4.trans.shared.b16 {%0,%1,%2,%3}, [%4];"
        : "=r"(r[0]), "=r"(r[1]), "=r"(r[2]), "=r"(r[3]) : "r"(a));
}
__device__ __forceinline__ void mma16816(float4& c, const uint32_t* a, uint32_t b0, uint32_t b1) {
    asm volatile(
        "mma.sync.aligned.m16n8k16.row.col.f32.bf16.bf16.f32 "
        "{%0,%1,%2,%3}, {%4,%5,%6,%7}, {%8,%9}, {%0,%1,%2,%3};"
        : "+f"(c.x), "+f"(c.y), "+f"(c.z), "+f"(c.w)
        : "r"(a[0]), "r"(a[1]), "r"(a[2]), "r"(a[3]), "r"(b0), "r"(b1));
}
__device__ __forceinline__ void cp_async16(uint32_t dst, const void* src) {
    asm volatile("{ .reg .u64 g; cvta.to.global.u64 g, %1; cp.async.cg.shared.global [%0], [g], 16; }"
        :: "r"(dst), "l"(src));
}
#define CP_COMMIT() asm volatile("cp.async.commit_group;" ::: "memory")
#define CP_WAIT0()  asm volatile("cp.async.wait_group 0;" ::: "memory")

// Index dtype sniff: int64 iff all sampled high words are zero.
__device__ __forceinline__ int sniff_is64(const void* items_raw, int tid) {
    const unsigned int* iw = (const unsigned int*)items_raw;
    int any = (tid < 256) ? (iw[2 * tid + 1] != 0u) : 0;
    return __syncthreads_or(any) == 0;
}
__device__ __forceinline__ int load_idx(const void* raw, int i, int is64) {
    return is64 ? (int)((const long long*)raw)[i] : ((const int*)raw)[i];
}

// ---------------- setup: E -> bf16 hi/lo, swizzled smem image in gmem ----------------
__global__ void setup_b_kernel(const float* __restrict__ user_emb) {
    const int c = blockIdx.x;           // chunk 0..156
    const int t = threadIdx.x;
    #pragma unroll
    for (int i = 0; i < 4; i++) {
        int e   = t + i * 256;          // 0..1023
        int row = e >> 4;               // 0..63 (u local)
        int q   = e & 15;               // float4 group along d
        int u   = c * CK + row;
        float4 v = (u < NUM_USERS) ? *(const float4*)&user_emb[(size_t)u * EMBED_DIM + q * 4]
                                   : make_float4(0.f, 0.f, 0.f, 0.f);
        uint32_t h0 = pack_bf2(v.x, v.y), h1 = pack_bf2(v.z, v.w);
        uint32_t l0 = pack_bf2(v.x - bfu_lo(h0), v.y - bfu_hi(h0));
        uint32_t l1 = pack_bf2(v.z - bfu_lo(h1), v.w - bfu_hi(h1));
        uint32_t off = (uint32_t)((q * 8) ^ ((row & 7) << 4));
        size_t base = (size_t)(c * CK + row) * 128 + off;
        *(uint2*)(g_Bhi + base) = make_uint2(h0, h1);
        *(uint2*)(g_Blo + base) = make_uint2(l0, l1);
    }
}

// ---------------- fused kernel ----------------
__global__ __launch_bounds__(256, 2)
void bpr_kernel(const float* __restrict__ user_emb,
                const float* __restrict__ item_emb,
                const float* __restrict__ social,
                const void*  __restrict__ users_raw,
                const void*  __restrict__ items_raw,
                float* __restrict__ out)
{
    extern __shared__ __align__(16) char dsm[];
    __shared__ int sU[TM];
    __shared__ int sI[TM];
    __shared__ unsigned int s_old;

    const uint32_t sb  = smem_u32(dsm);
    const int tid  = threadIdx.x;
    const int wid  = tid >> 5;
    const int lane = tid & 31;
    const int b0    = blockIdx.x * TM;
    const int split = blockIdx.y;

    const int is64 = sniff_is64(items_raw, tid);
    if (tid < TM) {
        sU[tid] = load_idx(users_raw, b0 + tid, is64);
        sI[tid] = load_idx(items_raw, b0 + tid, is64);
    }
    __syncthreads();

    // ---- A staging geometry ----
    const int arow  = tid >> 1;          // 0..127: A row (b)
    const int ahalf = tid & 1;           // which 32-u half
    const float* wrow = social + (size_t)sU[arow] * NUM_USERS;

    // ---- ldmatrix geometry ----
    const int asub = lane >> 3, ar = lane & 7;
    const int aRow = wid * 16 + (asub & 1) * 8 + ar;
    const uint32_t aKpart = (uint32_t)((asub >> 1) * 16);
    const uint32_t aXor   = (uint32_t)((aRow & 7) << 4);
    const uint32_t aRowB  = (uint32_t)(aRow * 128);

    const int bm = lane >> 3, br = lane & 7;
    const uint32_t bRowByte = (uint32_t)(((bm & 1) * 8 + br) * 128);
    const int      bJoff    = bm >> 1;
    const uint32_t bXor     = (uint32_t)(br << 4);

    float4 acc[8];
    #pragma unroll
    for (int n = 0; n < 8; n++) acc[n] = make_float4(0.f, 0.f, 0.f, 0.f);

    // ---- prologue: stage chunk `split` into buf 0 ----
    {
        const int u0 = split * CK;
        // B via cp.async (swizzle baked in gmem image)
        #pragma unroll
        for (int i = 0; i < 2; i++) {
            uint32_t off = (uint32_t)(tid + i * 256) * 16;   // (row*8+m)*16
            size_t gb = (size_t)split * (CK * 128) + off;
            cp_async16(sb + OFF_BHI + off, g_Bhi + gb);
            cp_async16(sb + OFF_BLO + off, g_Blo + gb);
        }
        CP_COMMIT();
        // A: LDG -> convert -> STS
        #pragma unroll
        for (int j = 0; j < 4; j++) {
            int col = u0 + ahalf * 32 + j * 8;
            float4 a = (col     < NUM_USERS) ? *(const float4*)(wrow + col)     : make_float4(0,0,0,0);
            float4 b = (col + 4 < NUM_USERS) ? *(const float4*)(wrow + col + 4) : make_float4(0,0,0,0);
            uint32_t h0 = pack_bf2(a.x, a.y), h1 = pack_bf2(a.z, a.w);
            uint32_t h2 = pack_bf2(b.x, b.y), h3 = pack_bf2(b.z, b.w);
            uint32_t l0 = pack_bf2(a.x - bfu_lo(h0), a.y - bfu_hi(h0));
            uint32_t l1 = pack_bf2(a.z - bfu_lo(h1), a.w - bfu_hi(h1));
            uint32_t l2 = pack_bf2(b.x - bfu_lo(h2), b.y - bfu_hi(h2));
            uint32_t l3 = pack_bf2(b.z - bfu_lo(h3), b.w - bfu_hi(h3));
            uint32_t off = (uint32_t)(arow * 128) + (uint32_t)(((ahalf * 64 + j * 16)) ^ ((arow & 7) << 4));
            sts16(sb + OFF_AHI + off, h0, h1, h2, h3);
            sts16(sb + OFF_ALO + off, l0, l1, l2, l3);
        }
        CP_WAIT0();
    }
    __syncthreads();

    // ---- mainloop ----
    int buf = 0;
    for (int c = split; c < NCH; c += SPLITS) {
        const int cn = c + SPLITS;
        const bool more = (cn < NCH);

        // issue next B cp.async into other buffer; prefetch next A into regs
        float4 wa[8];
        if (more) {
            const uint32_t bo = sb + (buf ? 0 : BUF_STRIDE);
            #pragma unroll
            for (int i = 0; i < 2; i++) {
                uint32_t off = (uint32_t)(tid + i * 256) * 16;
                size_t gb = (size_t)cn * (CK * 128) + off;
                cp_async16(bo + OFF_BHI + off, g_Bhi + gb);
                cp_async16(bo + OFF_BLO + off, g_Blo + gb);
            }
            CP_COMMIT();
            const int u0 = cn * CK;
            #pragma unroll
            for (int j = 0; j < 4; j++) {
                int col = u0 + ahalf * 32 + j * 8;
                wa[2*j]   = (col     < NUM_USERS) ? *(const float4*)(wrow + col)     : make_float4(0,0,0,0);
                wa[2*j+1] = (col + 4 < NUM_USERS) ? *(const float4*)(wrow + col + 4) : make_float4(0,0,0,0);
            }
        }

        // compute on current buffer (pass-major MMA ordering: RAW distance 8)
        {
            const uint32_t bo = sb + (buf ? BUF_STRIDE : 0);
            const uint32_t AhB = bo + OFF_AHI + aRowB;
            const uint32_t AlB = bo + OFF_ALO + aRowB;
            const uint32_t BhB = bo + OFF_BHI + bRowByte;
            const uint32_t BlB = bo + OFF_BLO + bRowByte;
            #pragma unroll
            for (int ks = 0; ks < 4; ks++) {
                uint32_t aH[4], aL[4], bH[16], bL[16];
                const uint32_t ka = (uint32_t)((ks * 32 + aKpart)) ^ aXor;
                ldsm_x4(aH, AhB + ka);
                ldsm_x4(aL, AlB + ka);
                const uint32_t kb = (uint32_t)(ks * 2048);
                #pragma unroll
                for (int p = 0; p < 4; p++) {
                    const uint32_t colsw = (uint32_t)(((2 * p + bJoff) * 16)) ^ bXor;
                    ldsm_x4t(&bH[4 * p], BhB + kb + colsw);
                    ldsm_x4t(&bL[4 * p], BlB + kb + colsw);
                }
                #pragma unroll
                for (int j = 0; j < 8; j++) mma16816(acc[j], aH, bH[2*j], bH[2*j+1]);
                #pragma unroll
                for (int j = 0; j < 8; j++) mma16816(acc[j], aH, bL[2*j], bL[2*j+1]);
                #pragma unroll
                for (int j = 0; j < 8; j++) mma16816(acc[j], aL, bH[2*j], bH[2*j+1]);
            }
        }

        // convert+store next A into other buffer; make sure next B landed
        if (more) {
            const uint32_t bo = sb + (buf ? 0 : BUF_STRIDE);
            #pragma unroll
            for (int j = 0; j < 4; j++) {
                float4 a = wa[2*j], b = wa[2*j+1];
                uint32_t h0 = pack_bf2(a.x, a.y), h1 = pack_bf2(a.z, a.w);
                uint32_t h2 = pack_bf2(b.x, b.y), h3 = pack_bf2(b.z, b.w);
                uint32_t l0 = pack_bf2(a.x - bfu_lo(h0), a.y - bfu_hi(h0));
                uint32_t l1 = pack_bf2(a.z - bfu_lo(h1), a.w - bfu_hi(h1));
                uint32_t l2 = pack_bf2(b.x - bfu_lo(h2), b.y - bfu_hi(h2));
                uint32_t l3 = pack_bf2(b.z - bfu_lo(h3), b.w - bfu_hi(h3));
                uint32_t off = (uint32_t)(arow * 128) + (uint32_t)(((ahalf * 64 + j * 16)) ^ ((arow & 7) << 4));
                sts16(bo + OFF_AHI + off, h0, h1, h2, h3);
                sts16(bo + OFF_ALO + off, l0, l1, l2, l3);
            }
            CP_WAIT0();
        }
        __syncthreads();
        buf ^= 1;
    }

    // ---- epilogue: dot with bi, reduce across the 4 lanes per row ----
    {
        const int r0 = wid * 16 + (lane >> 2);
        const int r1 = r0 + 8;
        const float* ip0 = item_emb + (size_t)sI[r0] * EMBED_DIM;
        const float* ip1 = item_emb + (size_t)sI[r1] * EMBED_DIM;
        const int cbase = (lane & 3) * 2;
        float v0 = 0.f, v1 = 0.f;
        #pragma unroll
        for (int n = 0; n < 8; n++) {
            const int cn = n * 8 + cbase;
            float2 e0 = *(const float2*)(ip0 + cn);
            float2 e1 = *(const float2*)(ip1 + cn);
            v0 += acc[n].x * e0.x + acc[n].y * e0.y;
            v1 += acc[n].z * e1.x + acc[n].w * e1.y;
        }
        v0 += __shfl_xor_sync(0xffffffffu, v0, 1);
        v0 += __shfl_xor_sync(0xffffffffu, v0, 2);
        v1 += __shfl_xor_sync(0xffffffffu, v1, 1);
        v1 += __shfl_xor_sync(0xffffffffu, v1, 2);
        if ((lane & 3) == 0) {
            g_partials[split][b0 + r0] = v0;
            g_partials[split][b0 + r1] = v1;
        }
    }
    __syncthreads();

    // ---- last split for this b-tile finishes: fixed-order sum + pos term ----
    if (tid == 0) {
        __threadfence();
        s_old = atomicAdd(&g_cnt[blockIdx.x], 1u);
    }
    __syncthreads();
    if (s_old == SPLITS - 1) {
        __threadfence();
        if (tid < TM) {
            const int b = b0 + tid;
            float s = 0.f;
            #pragma unroll
            for (int p = 0; p < SPLITS; p++) s += g_partials[p][b];
            const float4* ue = (const float4*)(user_emb + (size_t)sU[tid] * EMBED_DIM);
            const float4* ie = (const float4*)(item_emb + (size_t)sI[tid] * EMBED_DIM);
            float d = 0.f;
            #pragma unroll
            for (int k = 0; k < 16; k++) {
                float4 a = ue[k], c = ie[k];
                d += a.x * c.x + a.y * c.y + a.z * c.z + a.w * c.w;
            }
            out[b] = s + d;
        }
        __syncthreads();
        if (tid == 0) g_cnt[blockIdx.x] = 0u;   // self-reset for graph replay
    }
}

extern "C" void kernel_launch(void* const* d_in, const int* in_sizes, int n_in,
                              void* d_out, int out_size)
{
    const float* user_emb = (const float*)d_in[0];   // [10000, 64]
    const float* item_emb = (const float*)d_in[1];   // [100000, 64]
    const float* social   = (const float*)d_in[2];   // [10000, 10000]
    const void*  users    = d_in[3];                 // [4096] idx
    const void*  items    = d_in[4];                 // [4096] idx

    cudaFuncSetAttribute((const void*)bpr_kernel,
                         cudaFuncAttributeMaxDynamicSharedMemorySize, DSM_SIZE);

    setup_b_kernel<<<NCH, 256>>>(user_emb);

    dim3 grid(NTILES, SPLITS);   // 32 x 9 = 288 CTAs
    bpr_kernel<<<grid, 256, DSM_SIZE>>>(user_emb, item_emb, social, users, items, (float*)d_out);
}

// round 11
// speedup vs baseline: 2.5678x; 2.5678x over previous
#include <cuda_runtime.h>
#include <cstdint>
#include <cstddef>

#define NUM_USERS 10000
#define EMBED_DIM 64
#define BATCH     4096
#define TM        128            // b rows per CTA
#define CK        64             // u per chunk (K per stage)
#define SPLITS    9
#define NCH       157            // ceil(10000/64)
#define NTILES    (BATCH / TM)   // 32

// smem: A = raw fp32 W tile [128][68f pitch], B = tf32 E tile [64][72f pitch]
#define A_PITCH_B 272            // 68 floats: bank = 4r+k -> conflict-free A frags
#define B_PITCH_B 288            // 72 floats: bank = 8k+c -> conflict-free B frags
#define OFF_A     0
#define A_BYTES   (TM * A_PITCH_B)        // 34816
#define OFF_B     A_BYTES
#define B_BYTES   (CK * B_PITCH_B)        // 18432
#define BUF_STRIDE (A_BYTES + B_BYTES)    // 53248
#define DSM_SIZE  (2 * BUF_STRIDE)        // 106496 (occ 2 -> 208KB/SM)

// Precomputed E, tf32-rounded (stored as f32 bit patterns), chunk-major [157][64][64]
__device__ __align__(16) uint32_t g_Bt[NCH * CK * EMBED_DIM];
__device__ float        g_partials[SPLITS][BATCH];
__device__ unsigned int g_cnt[NTILES];

// ---------------- helpers ----------------
__device__ __forceinline__ uint32_t smem_u32(const void* p) {
    uint32_t a;
    asm("{ .reg .u64 t; cvta.to.shared.u64 t, %1; cvt.u32.u64 %0, t; }" : "=r"(a) : "l"(p));
    return a;
}
__device__ __forceinline__ uint32_t f2tf(float f) {
    uint32_t r;
    asm("cvt.rna.tf32.f32 %0, %1;" : "=r"(r) : "f"(f));
    return r;
}
__device__ __forceinline__ void lds_f32(float& d, uint32_t a) {
    asm volatile("ld.shared.f32 %0, [%1];" : "=f"(d) : "r"(a));
}
__device__ __forceinline__ void lds_u32(uint32_t& d, uint32_t a) {
    asm volatile("ld.shared.b32 %0, [%1];" : "=r"(d) : "r"(a));
}
__device__ __forceinline__ void cp_async16(uint32_t dst, const void* src) {
    asm volatile("{ .reg .u64 g; cvta.to.global.u64 g, %1; cp.async.cg.shared.global [%0], [g], 16; }"
        :: "r"(dst), "l"(src));
}
__device__ __forceinline__ void cp_async16z(uint32_t dst, const void* src, uint32_t sz) {
    asm volatile("{ .reg .u64 g; cvta.to.global.u64 g, %1; cp.async.cg.shared.global [%0], [g], 16, %2; }"
        :: "r"(dst), "l"(src), "r"(sz));
}
#define CP_COMMIT() asm volatile("cp.async.commit_group;" ::: "memory")
#define CP_WAIT0()  asm volatile("cp.async.wait_group 0;" ::: "memory")

__device__ __forceinline__ void mma_tf32(float4& c, const uint32_t* a, uint32_t b0, uint32_t b1) {
    asm volatile(
        "mma.sync.aligned.m16n8k8.row.col.f32.tf32.tf32.f32 "
        "{%0,%1,%2,%3}, {%4,%5,%6,%7}, {%8,%9}, {%0,%1,%2,%3};"
        : "+f"(c.x), "+f"(c.y), "+f"(c.z), "+f"(c.w)
        : "r"(a[0]), "r"(a[1]), "r"(a[2]), "r"(a[3]), "r"(b0), "r"(b1));
}

// Index dtype sniff: int64 iff all sampled high words are zero.
__device__ __forceinline__ int sniff_is64(const void* items_raw, int tid) {
    const unsigned int* iw = (const unsigned int*)items_raw;
    int any = (tid < 256) ? (iw[2 * tid + 1] != 0u) : 0;
    return __syncthreads_or(any) == 0;
}
__device__ __forceinline__ int load_idx(const void* raw, int i, int is64) {
    return is64 ? (int)((const long long*)raw)[i] : ((const int*)raw)[i];
}

// ---------------- setup: E -> tf32(rna), chunk-major image ----------------
__global__ void setup_b_kernel(const float* __restrict__ user_emb) {
    const int c = blockIdx.x;           // chunk 0..156
    const int t = threadIdx.x;
    #pragma unroll
    for (int i = 0; i < 4; i++) {
        int e   = t + i * 256;          // 0..1023
        int row = e >> 4;               // u local 0..63
        int q   = e & 15;               // float4 group along d
        int u   = c * CK + row;
        float4 v = (u < NUM_USERS) ? *(const float4*)&user_emb[(size_t)u * EMBED_DIM + q * 4]
                                   : make_float4(0.f, 0.f, 0.f, 0.f);
        uint4 o = make_uint4(f2tf(v.x), f2tf(v.y), f2tf(v.z), f2tf(v.w));
        *(uint4*)&g_Bt[((size_t)c * CK + row) * EMBED_DIM + q * 4] = o;
    }
}

// ---------------- fused kernel: single-pass tf32 GEMM + epilogue ----------------
__global__ __launch_bounds__(256, 2)
void bpr_kernel(const float* __restrict__ user_emb,
                const float* __restrict__ item_emb,
                const float* __restrict__ social,
                const void*  __restrict__ users_raw,
                const void*  __restrict__ items_raw,
                float* __restrict__ out)
{
    extern __shared__ __align__(16) char dsm[];
    __shared__ int sU[TM];
    __shared__ int sI[TM];
    __shared__ unsigned int s_old;

    const uint32_t sb  = smem_u32(dsm);
    const int tid  = threadIdx.x;
    const int wid  = tid >> 5;
    const int lane = tid & 31;
    const int b0    = blockIdx.x * TM;
    const int split = blockIdx.y;

    const int is64 = sniff_is64(items_raw, tid);
    if (tid < TM) {
        sU[tid] = load_idx(users_raw, b0 + tid, is64);
        sI[tid] = load_idx(items_raw, b0 + tid, is64);
    }
    __syncthreads();

    // ---- A staging: thread covers rows strow+16p, 16B segment scol16 (coalesced 256B rows) ----
    const int strow  = tid >> 4;         // 0..15
    const int scol16 = tid & 15;
    const float* aSrc[8];
    #pragma unroll
    for (int p = 0; p < 8; p++)
        aSrc[p] = social + (size_t)sU[strow + p * 16] * NUM_USERS + scol16 * 4;

    // ---- fragment geometry (per lane) ----
    const uint32_t aFragBase = (uint32_t)((wid * 16 + (lane >> 2)) * A_PITCH_B + (lane & 3) * 4);
    const uint32_t bFragBase = (uint32_t)((lane & 3) * B_PITCH_B + (lane >> 2) * 4);

    float4 acc[8];
    #pragma unroll
    for (int n = 0; n < 8; n++) acc[n] = make_float4(0.f, 0.f, 0.f, 0.f);

    // ---- prologue: stage chunk `split` into buf 0 ----
    {
        const int u0   = split * CK;
        const int colu = u0 + scol16 * 4;
        int rem = (NUM_USERS - colu) * 4;
        uint32_t sz = rem >= 16 ? 16u : (rem > 0 ? (uint32_t)rem : 0u);
        const float* srcbase = (sz == 0) ? aSrc[0] : (aSrc[0] + u0);
        #pragma unroll
        for (int p = 0; p < 8; p++) {
            const float* s = (sz == 0) ? aSrc[p] : (aSrc[p] + u0);
            cp_async16z(sb + OFF_A + (uint32_t)((strow + p * 16) * A_PITCH_B + scol16 * 16), s, sz);
        }
        (void)srcbase;
        #pragma unroll
        for (int p = 0; p < 4; p++) {
            int idx = tid + p * 256;                 // 0..1023
            uint32_t row = (uint32_t)(idx >> 4), c16 = (uint32_t)(idx & 15);
            cp_async16(sb + OFF_B + row * B_PITCH_B + c16 * 16,
                       g_Bt + (size_t)split * (CK * EMBED_DIM) + (size_t)idx * 4);
        }
        CP_COMMIT();
        CP_WAIT0();
    }
    __syncthreads();

    // ---- mainloop ----
    int buf = 0;
    for (int c = split; c < NCH; c += SPLITS) {
        const int cn = c + SPLITS;
        const bool more = (cn < NCH);

        // stage next chunk into other buffer (async, overlaps compute)
        if (more) {
            const uint32_t bo = (uint32_t)((buf ? 0 : BUF_STRIDE));
            const int u0   = cn * CK;
            const int colu = u0 + scol16 * 4;
            int rem = (NUM_USERS - colu) * 4;
            uint32_t sz = rem >= 16 ? 16u : (rem > 0 ? (uint32_t)rem : 0u);
            #pragma unroll
            for (int p = 0; p < 8; p++) {
                const float* s = (sz == 0) ? aSrc[p] : (aSrc[p] + u0);
                cp_async16z(sb + bo + OFF_A + (uint32_t)((strow + p * 16) * A_PITCH_B + scol16 * 16), s, sz);
            }
            #pragma unroll
            for (int p = 0; p < 4; p++) {
                int idx = tid + p * 256;
                uint32_t row = (uint32_t)(idx >> 4), c16 = (uint32_t)(idx & 15);
                cp_async16(sb + bo + OFF_B + row * B_PITCH_B + c16 * 16,
                           g_Bt + (size_t)cn * (CK * EMBED_DIM) + (size_t)idx * 4);
            }
            CP_COMMIT();
        }

        // compute on current buffer: 8 k-steps x 8 n-tiles, single pass
        {
            const uint32_t bo = (uint32_t)(buf ? BUF_STRIDE : 0);
            const uint32_t aB = sb + bo + OFF_A + aFragBase;
            const uint32_t bB = sb + bo + OFF_B + bFragBase;
            #pragma unroll
            for (int ks = 0; ks < 8; ks++) {
                float f0, f1, f2, f3;
                const uint32_t ka = aB + (uint32_t)(ks * 32);
                lds_f32(f0, ka);
                lds_f32(f1, ka + 8 * A_PITCH_B);
                lds_f32(f2, ka + 16);
                lds_f32(f3, ka + 16 + 8 * A_PITCH_B);
                uint32_t a[4] = { f2tf(f0), f2tf(f1), f2tf(f2), f2tf(f3) };
                uint32_t bb[16];
                const uint32_t kb = bB + (uint32_t)(ks * 8 * B_PITCH_B);
                #pragma unroll
                for (int j = 0; j < 8; j++) {
                    lds_u32(bb[2 * j],     kb + (uint32_t)(j * 32));
                    lds_u32(bb[2 * j + 1], kb + (uint32_t)(4 * B_PITCH_B + j * 32));
                }
                #pragma unroll
                for (int j = 0; j < 8; j++)
                    mma_tf32(acc[j], a, bb[2 * j], bb[2 * j + 1]);
            }
        }

        if (more) CP_WAIT0();
        __syncthreads();
        buf ^= 1;
    }

    // ---- epilogue: dot with bi, reduce across 4 lanes per row ----
    {
        const int r0 = wid * 16 + (lane >> 2);
        const int r1 = r0 + 8;
        const float* ip0 = item_emb + (size_t)sI[r0] * EMBED_DIM;
        const float* ip1 = item_emb + (size_t)sI[r1] * EMBED_DIM;
        const int cbase = (lane & 3) * 2;
        float v0 = 0.f, v1 = 0.f;
        #pragma unroll
        for (int n = 0; n < 8; n++) {
            const int cn = n * 8 + cbase;
            float2 e0 = *(const float2*)(ip0 + cn);
            float2 e1 = *(const float2*)(ip1 + cn);
            v0 += acc[n].x * e0.x + acc[n].y * e0.y;
            v1 += acc[n].z * e1.x + acc[n].w * e1.y;
        }
        v0 += __shfl_xor_sync(0xffffffffu, v0, 1);
        v0 += __shfl_xor_sync(0xffffffffu, v0, 2);
        v1 += __shfl_xor_sync(0xffffffffu, v1, 1);
        v1 += __shfl_xor_sync(0xffffffffu, v1, 2);
        if ((lane & 3) == 0) {
            g_partials[split][b0 + r0] = v0;
            g_partials[split][b0 + r1] = v1;
        }
    }
    __syncthreads();

    // ---- last split for this b-tile: fixed-order sum + pos term (deterministic) ----
    if (tid == 0) {
        __threadfence();
        s_old = atomicAdd(&g_cnt[blockIdx.x], 1u);
    }
    __syncthreads();
    if (s_old == SPLITS - 1) {
        __threadfence();
        if (tid < TM) {
            const int b = b0 + tid;
            float s = 0.f;
            #pragma unroll
            for (int p = 0; p < SPLITS; p++) s += g_partials[p][b];
            const float4* ue = (const float4*)(user_emb + (size_t)sU[tid] * EMBED_DIM);
            const float4* ie = (const float4*)(item_emb + (size_t)sI[tid] * EMBED_DIM);
            float d = 0.f;
            #pragma unroll
            for (int k = 0; k < 16; k++) {
                float4 a = ue[k], c2 = ie[k];
                d += a.x * c2.x + a.y * c2.y + a.z * c2.z + a.w * c2.w;
            }
            out[b] = s + d;
        }
        __syncthreads();
        if (tid == 0) g_cnt[blockIdx.x] = 0u;   // self-reset for graph replay
    }
}

extern "C" void kernel_launch(void* const* d_in, const int* in_sizes, int n_in,
                              void* d_out, int out_size)
{
    const float* user_emb = (const float*)d_in[0];   // [10000, 64]
    const float* item_emb = (const float*)d_in[1];   // [100000, 64]
    const float* social   = (const float*)d_in[2];   // [10000, 10000]
    const void*  users    = d_in[3];                 // [4096] idx
    const void*  items    = d_in[4];                 // [4096] idx

    cudaFuncSetAttribute((const void*)bpr_kernel,
                         cudaFuncAttributeMaxDynamicSharedMemorySize, DSM_SIZE);

    setup_b_kernel<<<NCH, 256>>>(user_emb);

    dim3 grid(NTILES, SPLITS);   // 32 x 9 = 288 CTAs, one wave @ occ 2
    bpr_kernel<<<grid, 256, DSM_SIZE>>>(user_emb, item_emb, social, users, items, (float*)d_out);
}